// round 1
// baseline (speedup 1.0000x reference)
#include <cuda_runtime.h>
#include <cstdint>

#define D_MODEL  1024
#define D_STATE  128
#define D_INNER  2048
#define HEADS    1024
#define PROJ_OUT 5376
#define BATCH    2
#define SEQ      2048
#define NTOK     (BATCH*SEQ)   // 4096

// Column offsets inside zxbcdt (per jnp.split): x[0:2048], z[2048:4096],
// B[4096:4224], C[4224:4352], dt[4352:5376]
#define OFF_Z  2048
#define OFF_B  4096
#define OFF_C  4224
#define OFF_DT 4352

// ---------------- scratch (no allocation allowed -> device globals) ----------
__device__ float g_xn    [(size_t)NTOK * D_MODEL];   // 16 MB
__device__ float g_zxbcdt[(size_t)NTOK * PROJ_OUT];  // 88 MB
__device__ float g_dtx   [(size_t)NTOK * D_INNER];   // 32 MB  dt*silu(conv(x))
__device__ float g_zsil  [(size_t)NTOK * D_INNER];   // 32 MB  silu(z)
__device__ float g_decay [(size_t)NTOK * HEADS];     // 16 MB  exp(dt*A)
__device__ float g_yg    [(size_t)NTOK * D_INNER];   // 32 MB  y * silu(z)

// ---------------- packed f32x2 helpers (sm_100+) -----------------------------
__device__ __forceinline__ unsigned long long pk2(float x, float y) {
    unsigned long long r;
    asm("mov.b64 %0, {%1, %2};" : "=l"(r) : "f"(x), "f"(y));
    return r;
}
__device__ __forceinline__ void upk2(unsigned long long v, float& x, float& y) {
    asm("mov.b64 {%0, %1}, %2;" : "=f"(x), "=f"(y) : "l"(v));
}
__device__ __forceinline__ unsigned long long ffma2_(unsigned long long a,
                                                     unsigned long long b,
                                                     unsigned long long c) {
    unsigned long long d;
    asm("fma.rn.f32x2 %0, %1, %2, %3;" : "=l"(d) : "l"(a), "l"(b), "l"(c));
    return d;
}
__device__ __forceinline__ unsigned long long fmul2_(unsigned long long a,
                                                     unsigned long long b) {
    unsigned long long d;
    asm("mul.rn.f32x2 %0, %1, %2;" : "=l"(d) : "l"(a), "l"(b));
    return d;
}

// ---------------- 1. LayerNorm ------------------------------------------------
__global__ void __launch_bounds__(256) ln_kernel(const float* __restrict__ u,
                                                 const float* __restrict__ g,
                                                 const float* __restrict__ b) {
    __shared__ float sS[8], sQ[8], sMV[2];
    const int row = blockIdx.x;
    const int tid = threadIdx.x;
    const int warp = tid >> 5, lane = tid & 31;

    float4 v = *((const float4*)(u + (size_t)row * D_MODEL) + tid);
    float s = v.x + v.y + v.z + v.w;
    float q = v.x*v.x + v.y*v.y + v.z*v.z + v.w*v.w;
    #pragma unroll
    for (int off = 16; off > 0; off >>= 1) {
        s += __shfl_xor_sync(0xffffffffu, s, off);
        q += __shfl_xor_sync(0xffffffffu, q, off);
    }
    if (lane == 0) { sS[warp] = s; sQ[warp] = q; }
    __syncthreads();
    if (tid == 0) {
        float S = 0.f, Q = 0.f;
        #pragma unroll
        for (int i = 0; i < 8; ++i) { S += sS[i]; Q += sQ[i]; }
        float mean = S * (1.0f / D_MODEL);
        float var  = Q * (1.0f / D_MODEL) - mean * mean;
        sMV[0] = mean;
        sMV[1] = rsqrtf(var + 1e-5f);
    }
    __syncthreads();
    const float mean = sMV[0], rstd = sMV[1];
    float4 gg = ((const float4*)g)[tid];
    float4 bb = ((const float4*)b)[tid];
    float4 o;
    o.x = (v.x - mean) * rstd * gg.x + bb.x;
    o.y = (v.y - mean) * rstd * gg.y + bb.y;
    o.z = (v.z - mean) * rstd * gg.z + bb.z;
    o.w = (v.w - mean) * rstd * gg.w + bb.w;
    *((float4*)(g_xn + (size_t)row * D_MODEL) + tid) = o;
}

// ---------------- 2/5. SGEMM (128x128x8 tile, 8x8 per thread) ----------------
// PHASE 0: g_xn(4096x1024) @ W_in(1024x5376) -> g_zxbcdt
// PHASE 1: g_yg(4096x2048) @ W_out(2048x1024) + u -> out
template<int PHASE>
__global__ void __launch_bounds__(256) sgemm_kernel(const float* __restrict__ Bw,
                                                    const float* __restrict__ R,
                                                    float* __restrict__ Cout) {
    constexpr int N = (PHASE == 0) ? PROJ_OUT : D_MODEL;
    constexpr int K = (PHASE == 0) ? D_MODEL  : D_INNER;
    const float* __restrict__ A = (PHASE == 0) ? g_xn : g_yg;
    float* __restrict__ C = (PHASE == 0) ? g_zxbcdt : Cout;

    __shared__ float As[8][128];   // transposed: As[k][m]
    __shared__ float Bs[8][128];

    const int tid = threadIdx.x;
    const int bx = blockIdx.x, by = blockIdx.y;
    const int arow = tid >> 1, acol = (tid & 1) * 4;
    const int brow = tid >> 5, bcol = (tid & 31) * 4;
    const float* Ap = A  + (size_t)(by * 128 + arow) * K + acol;
    const float* Bp = Bw + (size_t)brow * N + bx * 128 + bcol;
    const int tr = (tid >> 4) * 8;
    const int tc = (tid & 15) * 8;

    float acc[8][8];
    #pragma unroll
    for (int i = 0; i < 8; ++i)
        #pragma unroll
        for (int j = 0; j < 8; ++j) acc[i][j] = 0.f;

    for (int k0 = 0; k0 < K; k0 += 8) {
        float4 av = *(const float4*)Ap;
        float4 bv = *(const float4*)Bp;
        __syncthreads();
        As[acol + 0][arow] = av.x;
        As[acol + 1][arow] = av.y;
        As[acol + 2][arow] = av.z;
        As[acol + 3][arow] = av.w;
        *(float4*)&Bs[brow][bcol] = bv;
        __syncthreads();
        Ap += 8;
        Bp += (size_t)8 * N;
        #pragma unroll
        for (int k = 0; k < 8; ++k) {
            float ar[8], br[8];
            *(float4*)&ar[0] = *(const float4*)&As[k][tr];
            *(float4*)&ar[4] = *(const float4*)&As[k][tr + 4];
            *(float4*)&br[0] = *(const float4*)&Bs[k][tc];
            *(float4*)&br[4] = *(const float4*)&Bs[k][tc + 4];
            #pragma unroll
            for (int i = 0; i < 8; ++i)
                #pragma unroll
                for (int j = 0; j < 8; ++j)
                    acc[i][j] += ar[i] * br[j];
        }
    }
    #pragma unroll
    for (int i = 0; i < 8; ++i) {
        size_t off = (size_t)(by * 128 + tr + i) * N + bx * 128 + tc;
        float4 c0 = make_float4(acc[i][0], acc[i][1], acc[i][2], acc[i][3]);
        float4 c1 = make_float4(acc[i][4], acc[i][5], acc[i][6], acc[i][7]);
        if (PHASE == 1) {
            float4 r0 = *(const float4*)&R[off];
            float4 r1 = *(const float4*)&R[off + 4];
            c0.x += r0.x; c0.y += r0.y; c0.z += r0.z; c0.w += r0.w;
            c1.x += r1.x; c1.y += r1.y; c1.z += r1.z; c1.w += r1.w;
        }
        *(float4*)&C[off]     = c0;
        *(float4*)&C[off + 4] = c1;
    }
}

// ---------------- 3. conv + silu + softplus(dt) + decay + silu(z) -------------
__global__ void __launch_bounds__(256) conv_dtx_kernel(const float* __restrict__ conv_w,
                                                       const float* __restrict__ conv_b,
                                                       const float* __restrict__ A_log) {
    const int idx = blockIdx.x * 256 + threadIdx.x;   // < NTOK*D_INNER
    const int c  = idx & (D_INNER - 1);
    const int bt = idx >> 11;
    const int t  = bt & (SEQ - 1);
    const float* row = g_zxbcdt + (size_t)bt * PROJ_OUT;

    float acc = conv_b[c];
    #pragma unroll
    for (int k = 0; k < 4; ++k) {
        int tt = t - 3 + k;
        if (tt >= 0)
            acc += conv_w[c * 4 + k] * g_zxbcdt[(size_t)(bt - 3 + k) * PROJ_OUT + c];
    }
    float xs = acc / (1.f + expf(-acc));          // silu(conv)
    int h = c >> 1;
    float dtraw = row[OFF_DT + h];
    float dtp = (dtraw > 20.f) ? dtraw : log1pf(expf(dtraw));  // softplus
    g_dtx[idx] = dtp * xs;
    float z = row[OFF_Z + c];
    g_zsil[idx] = z / (1.f + expf(-z));
    if (!(c & 1))
        g_decay[(size_t)bt * HEADS + h] = expf(dtp * (-expf(A_log[h])));
}

// ---------------- 4. SSM scan -------------------------------------------------
// 128 blocks = 2 batches x 64 head-groups of 16 heads. 8 warps/block,
// warp handles 2 heads; lane owns n = lane*4 .. lane*4+3 of the state,
// both p values, via packed f32x2 FMA. y reduced with 6-shfl split butterfly.
#define CHUNK 32
__global__ void __launch_bounds__(256, 1) scan_kernel() {
    __shared__ float sB[CHUNK][128];
    __shared__ float sC[CHUNK][128];
    __shared__ float sDec[CHUNK][16];
    __shared__ float sKx[CHUNK][32];
    __shared__ float sZ[CHUNK][32];

    const int tid = threadIdx.x;
    const int warp = tid >> 5, lane = tid & 31;
    const int batch = blockIdx.x >> 6;
    const int hbase = (blockIdx.x & 63) << 4;     // 16 heads per block
    const int lhA = warp << 1;                    // local head index of head A
    const int ni = lane << 2;

    unsigned long long a00 = 0, a01 = 0, a10 = 0, a11 = 0;   // head A state (p0/p1 x 2 pairs)
    unsigned long long b00 = 0, b01 = 0, b10 = 0, b11 = 0;   // head B state

    const float* zx = g_zxbcdt + (size_t)batch * SEQ * PROJ_OUT;
    const int sel = lane >> 3;
    const bool writer = (lane & 7) == 0;
    const int zloc = (lhA << 1) + sel;            // 0..31 local channel
    const size_t ybase = (size_t)batch * SEQ * D_INNER + ((size_t)hbase << 1) + zloc;

    for (int ch = 0; ch < SEQ / CHUNK; ++ch) {
        const int t0 = ch << 5;
        __syncthreads();
        {
            const float* rb = zx + (size_t)t0 * PROJ_OUT;
            #pragma unroll
            for (int i = tid; i < CHUNK * 32; i += 256) {     // B,C: 32 float4 per step
                int st = i >> 5, j = (i & 31) << 2;
                const float* p = rb + (size_t)st * PROJ_OUT;
                *(float4*)&sB[st][j] = *(const float4*)(p + OFF_B + j);
                *(float4*)&sC[st][j] = *(const float4*)(p + OFF_C + j);
            }
            #pragma unroll
            for (int i = tid; i < CHUNK * 16; i += 256) {
                int st = i >> 4, h = i & 15;
                sDec[st][h] = g_decay[(size_t)(batch * SEQ + t0 + st) * HEADS + hbase + h];
            }
            #pragma unroll
            for (int i = tid; i < CHUNK * 32; i += 256) {
                int st = i >> 5, j = i & 31;
                size_t gi = (size_t)(batch * SEQ + t0 + st) * D_INNER + ((size_t)hbase << 1) + j;
                sKx[st][j] = g_dtx[gi];
                sZ[st][j]  = g_zsil[gi];
            }
        }
        __syncthreads();

        #pragma unroll 2
        for (int tl = 0; tl < CHUNK; ++tl) {
            unsigned long long B01 = *(const unsigned long long*)&sB[tl][ni];
            unsigned long long B23 = *(const unsigned long long*)&sB[tl][ni + 2];
            unsigned long long C01 = *(const unsigned long long*)&sC[tl][ni];
            unsigned long long C23 = *(const unsigned long long*)&sC[tl][ni + 2];

            // head A update
            float decA = sDec[tl][lhA];
            float2 kxA = *(const float2*)&sKx[tl][lhA << 1];
            unsigned long long dA  = pk2(decA, decA);
            unsigned long long kA0 = pk2(kxA.x, kxA.x);
            unsigned long long kA1 = pk2(kxA.y, kxA.y);
            a00 = ffma2_(dA, a00, fmul2_(kA0, B01));
            a01 = ffma2_(dA, a01, fmul2_(kA0, B23));
            a10 = ffma2_(dA, a10, fmul2_(kA1, B01));
            a11 = ffma2_(dA, a11, fmul2_(kA1, B23));

            // head B update
            float decB = sDec[tl][lhA + 1];
            float2 kxB = *(const float2*)&sKx[tl][(lhA << 1) + 2];
            unsigned long long dB  = pk2(decB, decB);
            unsigned long long kB0 = pk2(kxB.x, kxB.x);
            unsigned long long kB1 = pk2(kxB.y, kxB.y);
            b00 = ffma2_(dB, b00, fmul2_(kB0, B01));
            b01 = ffma2_(dB, b01, fmul2_(kB0, B23));
            b10 = ffma2_(dB, b10, fmul2_(kB1, B01));
            b11 = ffma2_(dB, b11, fmul2_(kB1, B23));

            // dots: y = h . C  (per head, per p)
            unsigned long long dp;
            float fx, fy;
            dp = ffma2_(a01, C23, fmul2_(a00, C01)); upk2(dp, fx, fy); float y0 = fx + fy;
            dp = ffma2_(a11, C23, fmul2_(a10, C01)); upk2(dp, fx, fy); float y1 = fx + fy;
            dp = ffma2_(b01, C23, fmul2_(b00, C01)); upk2(dp, fx, fy); float y2 = fx + fy;
            dp = ffma2_(b11, C23, fmul2_(b10, C01)); upk2(dp, fx, fy); float y3 = fx + fy;

            // 6-shfl split-warp butterfly for 4 outputs
            float t0v = (lane < 16) ? y2 : y0;
            float u0 = __shfl_xor_sync(0xffffffffu, t0v, 16);
            if (lane < 16) y0 += u0; else y2 += u0;
            float t1v = (lane < 16) ? y3 : y1;
            float u1 = __shfl_xor_sync(0xffffffffu, t1v, 16);
            if (lane < 16) y1 += u1; else y3 += u1;
            float v0 = (lane < 16) ? y0 : y2;
            float v1 = (lane < 16) ? y1 : y3;
            float tv = (lane & 8) ? v0 : v1;
            float uv = __shfl_xor_sync(0xffffffffu, tv, 8);
            if (lane & 8) v1 += uv; else v0 += uv;
            float v = (lane & 8) ? v1 : v0;
            v += __shfl_xor_sync(0xffffffffu, v, 4);
            v += __shfl_xor_sync(0xffffffffu, v, 2);
            v += __shfl_xor_sync(0xffffffffu, v, 1);

            if (writer)
                g_yg[ybase + (size_t)(t0 + tl) * D_INNER] = v * sZ[tl][zloc];
        }
    }
}

// ---------------- launch ------------------------------------------------------
extern "C" void kernel_launch(void* const* d_in, const int* in_sizes, int n_in,
                              void* d_out, int out_size) {
    const float* u      = (const float*)d_in[0];
    const float* W_in   = (const float*)d_in[1];
    const float* conv_w = (const float*)d_in[2];
    const float* conv_b = (const float*)d_in[3];
    const float* W_out  = (const float*)d_in[4];
    const float* ln_g   = (const float*)d_in[5];
    const float* ln_b   = (const float*)d_in[6];
    const float* A_log  = (const float*)d_in[7];
    float* out = (float*)d_out;

    ln_kernel<<<NTOK, 256>>>(u, ln_g, ln_b);
    sgemm_kernel<0><<<dim3(PROJ_OUT / 128, NTOK / 128), 256>>>(W_in, nullptr, nullptr);
    conv_dtx_kernel<<<(NTOK * D_INNER) / 256, 256>>>(conv_w, conv_b, A_log);
    scan_kernel<<<128, 256>>>();
    sgemm_kernel<1><<<dim3(D_MODEL / 128, NTOK / 128), 256>>>(W_out, u, out);
}

// round 5
// speedup vs baseline: 1.6307x; 1.6307x over previous
#include <cuda_runtime.h>
#include <cuda_bf16.h>
#include <cstdint>

#define D_MODEL  1024
#define D_STATE  128
#define D_INNER  2048
#define HEADS    1024
#define PROJ_OUT 5376
#define BATCH    2
#define SEQ      2048
#define NTOK     (BATCH*SEQ)   // 4096

#define OFF_Z  2048
#define OFF_B  4096
#define OFF_C  4224
#define OFF_DT 4352

#define K2_1 3072          // 3 * D_MODEL  (split GEMM1 K)
#define K2_2 6144          // 3 * D_INNER  (split GEMM2 K)

// smem tile geometry: 128 rows x 32 k bf16, padded row stride 40 elems (80 B)
#define ROWB   80
#define TILEB  (128 * ROWB)          // 10240
#define STAGEB (2 * TILEB)           // 20480
#define GEMM_SMEM (3 * STAGEB)       // 61440

// ---------------- scratch (device globals) -----------------------------------
__device__ float g_zxbcdt[(size_t)NTOK * PROJ_OUT];
__device__ float g_dtx   [(size_t)NTOK * D_INNER];
__device__ float g_zsil  [(size_t)NTOK * D_INNER];
__device__ float g_decay [(size_t)NTOK * HEADS];
__device__ float g_yg    [(size_t)NTOK * D_INNER];
__device__ __nv_bfloat16 g_Ain [(size_t)NTOK * K2_1];      // [Ahi|Ahi|Alo] of ln(u)
__device__ __nv_bfloat16 g_Bin [(size_t)PROJ_OUT * K2_1];  // W_in^T split [Bhi|Blo|Bhi]
__device__ __nv_bfloat16 g_Ay  [(size_t)NTOK * K2_2];      // [Ahi|Ahi|Alo] of y*silu(z)
__device__ __nv_bfloat16 g_Bout[(size_t)D_MODEL * K2_2];   // W_out^T split

// ---------------- helpers -----------------------------------------------------
struct alignas(8) bf4 { __nv_bfloat16 v[4]; };

__device__ __forceinline__ uint32_t smem_u32(const void* p) {
    uint32_t a;
    asm("{ .reg .u64 t; cvta.to.shared.u64 t, %1; cvt.u32.u64 %0, t; }" : "=r"(a) : "l"(p));
    return a;
}
__device__ __forceinline__ void cp16(uint32_t s, const void* g) {
    asm volatile("cp.async.cg.shared.global [%0], [%1], 16;" :: "r"(s), "l"(g) : "memory");
}
#define CP_COMMIT() asm volatile("cp.async.commit_group;" ::: "memory")

__device__ __forceinline__ uint32_t lds32(uint32_t addr) {
    uint32_t v;
    asm volatile("ld.shared.b32 %0, [%1];" : "=r"(v) : "r"(addr));
    return v;
}
__device__ __forceinline__ void mma16816(float& d0, float& d1, float& d2, float& d3,
                                         uint32_t a0, uint32_t a1, uint32_t a2, uint32_t a3,
                                         uint32_t b0, uint32_t b1) {
    asm volatile("mma.sync.aligned.m16n8k16.row.col.f32.bf16.bf16.f32 "
                 "{%0,%1,%2,%3}, {%4,%5,%6,%7}, {%8,%9}, {%0,%1,%2,%3};"
                 : "+f"(d0), "+f"(d1), "+f"(d2), "+f"(d3)
                 : "r"(a0), "r"(a1), "r"(a2), "r"(a3), "r"(b0), "r"(b1));
}
__device__ __forceinline__ void split_bf16(float v, __nv_bfloat16& hi, __nv_bfloat16& lo) {
    hi = __float2bfloat16(v);
    lo = __float2bfloat16(v - __bfloat162float(hi));
}

// ---------------- 1. LayerNorm -> split bf16 A2 ------------------------------
__global__ void __launch_bounds__(256) ln_kernel(const float* __restrict__ u,
                                                 const float* __restrict__ g,
                                                 const float* __restrict__ b) {
    __shared__ float sS[8], sQ[8], sMV[2];
    const int row = blockIdx.x;
    const int tid = threadIdx.x;
    const int warp = tid >> 5, lane = tid & 31;

    float4 v = *((const float4*)(u + (size_t)row * D_MODEL) + tid);
    float s = v.x + v.y + v.z + v.w;
    float q = v.x*v.x + v.y*v.y + v.z*v.z + v.w*v.w;
    #pragma unroll
    for (int off = 16; off > 0; off >>= 1) {
        s += __shfl_xor_sync(0xffffffffu, s, off);
        q += __shfl_xor_sync(0xffffffffu, q, off);
    }
    if (lane == 0) { sS[warp] = s; sQ[warp] = q; }
    __syncthreads();
    if (tid == 0) {
        float S = 0.f, Q = 0.f;
        #pragma unroll
        for (int i = 0; i < 8; ++i) { S += sS[i]; Q += sQ[i]; }
        float mean = S * (1.0f / D_MODEL);
        float var  = Q * (1.0f / D_MODEL) - mean * mean;
        sMV[0] = mean;
        sMV[1] = rsqrtf(var + 1e-5f);
    }
    __syncthreads();
    const float mean = sMV[0], rstd = sMV[1];
    float4 gg = ((const float4*)g)[tid];
    float4 bb = ((const float4*)b)[tid];
    float o[4];
    o[0] = (v.x - mean) * rstd * gg.x + bb.x;
    o[1] = (v.y - mean) * rstd * gg.y + bb.y;
    o[2] = (v.z - mean) * rstd * gg.z + bb.z;
    o[3] = (v.w - mean) * rstd * gg.w + bb.w;
    bf4 H, L;
    #pragma unroll
    for (int j = 0; j < 4; ++j) split_bf16(o[j], H.v[j], L.v[j]);
    const size_t rb = (size_t)row * K2_1 + tid * 4;
    *(bf4*)(g_Ain + rb)              = H;
    *(bf4*)(g_Ain + rb + D_MODEL)    = H;
    *(bf4*)(g_Ain + rb + 2*D_MODEL)  = L;
}

// ---------------- weight transpose + split: W[K,N] -> B2[N, 3K] --------------
// Output array selected IN DEVICE CODE (host code must never name __device__ globals:
// on GB300/ATS the host shadow address is silently writable -> data lands in host RAM).
template<int PHASE>
__global__ void wconv_kernel(const float* __restrict__ W) {
    constexpr int K = PHASE ? D_INNER : D_MODEL;
    constexpr int N = PHASE ? D_MODEL : PROJ_OUT;
    __nv_bfloat16* __restrict__ Bo = PHASE ? g_Bout : g_Bin;

    __shared__ float t[32][33];
    const int tx = threadIdx.x, ty = threadIdx.y;
    const int n0 = blockIdx.x * 32, k0 = blockIdx.y * 32;
    t[ty][tx] = W[(size_t)(k0 + ty) * N + n0 + tx];
    __syncthreads();
    float v = t[tx][ty];                       // = W[k0+tx][n0+ty]
    __nv_bfloat16 hi, lo;
    split_bf16(v, hi, lo);
    const size_t r = (size_t)(n0 + ty) * 3 * K + k0 + tx;
    Bo[r]         = hi;
    Bo[r + K]     = lo;
    Bo[r + 2*K]   = hi;
}

// ---------------- y split: g_yg[4096,2048] -> g_Ay[4096,6144] ----------------
__global__ void __launch_bounds__(256) yconv_kernel() {
    const int idx = blockIdx.x * 256 + threadIdx.x;
    const float v = g_yg[idx];
    const int m = idx >> 11, c = idx & (D_INNER - 1);
    __nv_bfloat16 hi, lo;
    split_bf16(v, hi, lo);
    const size_t base = (size_t)m * K2_2 + c;
    g_Ay[base]              = hi;
    g_Ay[base + D_INNER]    = hi;
    g_Ay[base + 2*D_INNER]  = lo;
}

// ---------------- bf16 mma.sync GEMM (128x128x32, 3-stage cp.async) ----------
// Operand fetch: plain LDS.32 from padded layout (row stride 80 B, conflict-free).
// PHASE 0: g_Ain(4096 x 3072) @ g_Bin^T (5376 x 3072) -> g_zxbcdt fp32
// PHASE 1: g_Ay (4096 x 6144) @ g_Bout^T(1024 x 6144) + u -> out fp32
template<int PHASE>
__global__ void __launch_bounds__(256) gemm_mma(const float* __restrict__ R,
                                                float* __restrict__ Cout) {
    constexpr int K2 = PHASE ? K2_2 : K2_1;
    constexpr int NC = PHASE ? D_MODEL : PROJ_OUT;
    constexpr int NITER = K2 / 32;

    const __nv_bfloat16* Asrc = PHASE ? g_Ay  : g_Ain;
    const __nv_bfloat16* Bsrc = PHASE ? g_Bout : g_Bin;
    float* C = PHASE ? Cout : g_zxbcdt;

    extern __shared__ char smemraw[];
    const uint32_t sb = smem_u32(smemraw);

    const int tid = threadIdx.x;
    const int wid = tid >> 5, lane = tid & 31;
    const int wm = wid & 1, wn = wid >> 1;          // warp tile: 64 x 32
    const int m0 = blockIdx.y * 128, n0 = blockIdx.x * 128;
    const __nv_bfloat16* Ag = Asrc + (size_t)m0 * K2;
    const __nv_bfloat16* Bg = Bsrc + (size_t)n0 * K2;

    auto load_stage = [&](int it, int st) {
        const int k0 = it * 32;
        const uint32_t base = sb + st * STAGEB;
        #pragma unroll
        for (int i = 0; i < 2; ++i) {
            const int idx = tid + i * 256;          // 0..511 -> (row, chunk)
            const int row = idx >> 2, ch = idx & 3;
            const uint32_t off = row * ROWB + ch * 16;
            cp16(base         + off, Ag + (size_t)row * K2 + k0 + ch * 8);
            cp16(base + TILEB + off, Bg + (size_t)row * K2 + k0 + ch * 8);
        }
    };

    float acc[4][4][4];
    #pragma unroll
    for (int mt = 0; mt < 4; ++mt)
        #pragma unroll
        for (int nt = 0; nt < 4; ++nt)
            #pragma unroll
            for (int r = 0; r < 4; ++r) acc[mt][nt][r] = 0.f;

    load_stage(0, 0); CP_COMMIT();
    load_stage(1, 1); CP_COMMIT();

    // per-lane byte offset within a fragment group: row (lane>>2), k-pair (lane&3)
    const uint32_t frag = (lane >> 2) * ROWB + (lane & 3) * 4;
    const uint32_t a_base0 = wm * 64 * ROWB + frag;        // + mt*16*ROWB + ks*32
    const uint32_t b_base0 = wn * 32 * ROWB + frag;        // + nt*8*ROWB  + ks*32

    int st = 0;
    for (int it = 0; it < NITER; ++it) {
        asm volatile("cp.async.wait_group 1;" ::: "memory");
        __syncthreads();
        if (it + 2 < NITER) load_stage(it + 2, (st + 2) % 3);
        CP_COMMIT();

        const uint32_t abase = sb + st * STAGEB;
        const uint32_t bbase = abase + TILEB;
        #pragma unroll
        for (int ks = 0; ks < 2; ++ks) {
            uint32_t a[4][4], b[4][2];
            #pragma unroll
            for (int mt = 0; mt < 4; ++mt) {
                const uint32_t p = abase + a_base0 + mt * (16 * ROWB) + ks * 32;
                a[mt][0] = lds32(p);                    // (m,      k)
                a[mt][1] = lds32(p + 8 * ROWB);         // (m+8,    k)
                a[mt][2] = lds32(p + 16);               // (m,      k+8)
                a[mt][3] = lds32(p + 8 * ROWB + 16);    // (m+8,    k+8)
            }
            #pragma unroll
            for (int nt = 0; nt < 4; ++nt) {
                const uint32_t p = bbase + b_base0 + nt * (8 * ROWB) + ks * 32;
                b[nt][0] = lds32(p);                    // (n, k)
                b[nt][1] = lds32(p + 16);               // (n, k+8)
            }
            #pragma unroll
            for (int mt = 0; mt < 4; ++mt)
                #pragma unroll
                for (int nt = 0; nt < 4; ++nt)
                    mma16816(acc[mt][nt][0], acc[mt][nt][1], acc[mt][nt][2], acc[mt][nt][3],
                             a[mt][0], a[mt][1], a[mt][2], a[mt][3], b[nt][0], b[nt][1]);
        }
        st = (st + 1) % 3;
    }

    // epilogue
    const int rbase = m0 + wm * 64 + (lane >> 2);
    const int cbase = n0 + wn * 32 + 2 * (lane & 3);
    #pragma unroll
    for (int mt = 0; mt < 4; ++mt) {
        #pragma unroll
        for (int nt = 0; nt < 4; ++nt) {
            const int rr0 = rbase + mt * 16;
            const int cc  = cbase + nt * 8;
            float2 v0 = make_float2(acc[mt][nt][0], acc[mt][nt][1]);
            float2 v1 = make_float2(acc[mt][nt][2], acc[mt][nt][3]);
            if (PHASE == 1) {
                float2 r0 = *(const float2*)&R[(size_t)rr0 * NC + cc];
                float2 r1 = *(const float2*)&R[(size_t)(rr0 + 8) * NC + cc];
                v0.x += r0.x; v0.y += r0.y;
                v1.x += r1.x; v1.y += r1.y;
            }
            *(float2*)&C[(size_t)rr0 * NC + cc]       = v0;
            *(float2*)&C[(size_t)(rr0 + 8) * NC + cc] = v1;
        }
    }
}

// ---------------- conv + silu + softplus(dt) + decay + silu(z) ---------------
__global__ void __launch_bounds__(256) conv_dtx_kernel(const float* __restrict__ conv_w,
                                                       const float* __restrict__ conv_b,
                                                       const float* __restrict__ A_log) {
    const int idx = blockIdx.x * 256 + threadIdx.x;
    const int c  = idx & (D_INNER - 1);
    const int bt = idx >> 11;
    const int t  = bt & (SEQ - 1);
    const float* row = g_zxbcdt + (size_t)bt * PROJ_OUT;

    float acc = conv_b[c];
    #pragma unroll
    for (int k = 0; k < 4; ++k) {
        int tt = t - 3 + k;
        if (tt >= 0)
            acc += conv_w[c * 4 + k] * g_zxbcdt[(size_t)(bt - 3 + k) * PROJ_OUT + c];
    }
    float xs = acc / (1.f + expf(-acc));
    int h = c >> 1;
    float dtraw = row[OFF_DT + h];
    float dtp = (dtraw > 20.f) ? dtraw : log1pf(expf(dtraw));
    g_dtx[idx] = dtp * xs;
    float z = row[OFF_Z + c];
    g_zsil[idx] = z / (1.f + expf(-z));
    if (!(c & 1))
        g_decay[(size_t)bt * HEADS + h] = expf(dtp * (-expf(A_log[h])));
}

// ---------------- SSM scan ----------------------------------------------------
__device__ __forceinline__ unsigned long long pk2(float x, float y) {
    unsigned long long r;
    asm("mov.b64 %0, {%1, %2};" : "=l"(r) : "f"(x), "f"(y));
    return r;
}
__device__ __forceinline__ void upk2(unsigned long long v, float& x, float& y) {
    asm("mov.b64 {%0, %1}, %2;" : "=f"(x), "=f"(y) : "l"(v));
}
__device__ __forceinline__ unsigned long long ffma2_(unsigned long long a,
                                                     unsigned long long b,
                                                     unsigned long long c) {
    unsigned long long d;
    asm("fma.rn.f32x2 %0, %1, %2, %3;" : "=l"(d) : "l"(a), "l"(b), "l"(c));
    return d;
}
__device__ __forceinline__ unsigned long long fmul2_(unsigned long long a,
                                                     unsigned long long b) {
    unsigned long long d;
    asm("mul.rn.f32x2 %0, %1, %2;" : "=l"(d) : "l"(a), "l"(b));
    return d;
}

#define CHUNK 32
__global__ void __launch_bounds__(256, 1) scan_kernel() {
    __shared__ float sB[CHUNK][128];
    __shared__ float sC[CHUNK][128];
    __shared__ float sDec[CHUNK][16];
    __shared__ float sKx[CHUNK][32];
    __shared__ float sZ[CHUNK][32];

    const int tid = threadIdx.x;
    const int warp = tid >> 5, lane = tid & 31;
    const int batch = blockIdx.x >> 6;
    const int hbase = (blockIdx.x & 63) << 4;
    const int lhA = warp << 1;
    const int ni = lane << 2;

    unsigned long long a00 = 0, a01 = 0, a10 = 0, a11 = 0;
    unsigned long long b00 = 0, b01 = 0, b10 = 0, b11 = 0;

    const float* zx = g_zxbcdt + (size_t)batch * SEQ * PROJ_OUT;
    const int sel = lane >> 3;
    const bool writer = (lane & 7) == 0;
    const int zloc = (lhA << 1) + sel;
    const size_t ybase = (size_t)batch * SEQ * D_INNER + ((size_t)hbase << 1) + zloc;

    for (int ch = 0; ch < SEQ / CHUNK; ++ch) {
        const int t0 = ch << 5;
        __syncthreads();
        {
            const float* rb = zx + (size_t)t0 * PROJ_OUT;
            #pragma unroll
            for (int i = tid; i < CHUNK * 32; i += 256) {
                int st = i >> 5, j = (i & 31) << 2;
                const float* p = rb + (size_t)st * PROJ_OUT;
                *(float4*)&sB[st][j] = *(const float4*)(p + OFF_B + j);
                *(float4*)&sC[st][j] = *(const float4*)(p + OFF_C + j);
            }
            #pragma unroll
            for (int i = tid; i < CHUNK * 16; i += 256) {
                int st = i >> 4, h = i & 15;
                sDec[st][h] = g_decay[(size_t)(batch * SEQ + t0 + st) * HEADS + hbase + h];
            }
            #pragma unroll
            for (int i = tid; i < CHUNK * 32; i += 256) {
                int st = i >> 5, j = i & 31;
                size_t gi = (size_t)(batch * SEQ + t0 + st) * D_INNER + ((size_t)hbase << 1) + j;
                sKx[st][j] = g_dtx[gi];
                sZ[st][j]  = g_zsil[gi];
            }
        }
        __syncthreads();

        #pragma unroll 2
        for (int tl = 0; tl < CHUNK; ++tl) {
            unsigned long long B01 = *(const unsigned long long*)&sB[tl][ni];
            unsigned long long B23 = *(const unsigned long long*)&sB[tl][ni + 2];
            unsigned long long C01 = *(const unsigned long long*)&sC[tl][ni];
            unsigned long long C23 = *(const unsigned long long*)&sC[tl][ni + 2];

            float decA = sDec[tl][lhA];
            float2 kxA = *(const float2*)&sKx[tl][lhA << 1];
            unsigned long long dA  = pk2(decA, decA);
            unsigned long long kA0 = pk2(kxA.x, kxA.x);
            unsigned long long kA1 = pk2(kxA.y, kxA.y);
            a00 = ffma2_(dA, a00, fmul2_(kA0, B01));
            a01 = ffma2_(dA, a01, fmul2_(kA0, B23));
            a10 = ffma2_(dA, a10, fmul2_(kA1, B01));
            a11 = ffma2_(dA, a11, fmul2_(kA1, B23));

            float decB = sDec[tl][lhA + 1];
            float2 kxB = *(const float2*)&sKx[tl][(lhA << 1) + 2];
            unsigned long long dB  = pk2(decB, decB);
            unsigned long long kB0 = pk2(kxB.x, kxB.x);
            unsigned long long kB1 = pk2(kxB.y, kxB.y);
            b00 = ffma2_(dB, b00, fmul2_(kB0, B01));
            b01 = ffma2_(dB, b01, fmul2_(kB0, B23));
            b10 = ffma2_(dB, b10, fmul2_(kB1, B01));
            b11 = ffma2_(dB, b11, fmul2_(kB1, B23));

            unsigned long long dp;
            float fx, fy;
            dp = ffma2_(a01, C23, fmul2_(a00, C01)); upk2(dp, fx, fy); float y0 = fx + fy;
            dp = ffma2_(a11, C23, fmul2_(a10, C01)); upk2(dp, fx, fy); float y1 = fx + fy;
            dp = ffma2_(b01, C23, fmul2_(b00, C01)); upk2(dp, fx, fy); float y2 = fx + fy;
            dp = ffma2_(b11, C23, fmul2_(b10, C01)); upk2(dp, fx, fy); float y3 = fx + fy;

            float t0v = (lane < 16) ? y2 : y0;
            float u0 = __shfl_xor_sync(0xffffffffu, t0v, 16);
            if (lane < 16) y0 += u0; else y2 += u0;
            float t1v = (lane < 16) ? y3 : y1;
            float u1 = __shfl_xor_sync(0xffffffffu, t1v, 16);
            if (lane < 16) y1 += u1; else y3 += u1;
            float v0 = (lane < 16) ? y0 : y2;
            float v1 = (lane < 16) ? y1 : y3;
            float tv = (lane & 8) ? v0 : v1;
            float uv = __shfl_xor_sync(0xffffffffu, tv, 8);
            if (lane & 8) v1 += uv; else v0 += uv;
            float v = (lane & 8) ? v1 : v0;
            v += __shfl_xor_sync(0xffffffffu, v, 4);
            v += __shfl_xor_sync(0xffffffffu, v, 2);
            v += __shfl_xor_sync(0xffffffffu, v, 1);

            if (writer)
                g_yg[ybase + (size_t)(t0 + tl) * D_INNER] = v * sZ[tl][zloc];
        }
    }
}

// ---------------- launch ------------------------------------------------------
extern "C" void kernel_launch(void* const* d_in, const int* in_sizes, int n_in,
                              void* d_out, int out_size) {
    const float* u      = (const float*)d_in[0];
    const float* W_in   = (const float*)d_in[1];
    const float* conv_w = (const float*)d_in[2];
    const float* conv_b = (const float*)d_in[3];
    const float* W_out  = (const float*)d_in[4];
    const float* ln_g   = (const float*)d_in[5];
    const float* ln_b   = (const float*)d_in[6];
    const float* A_log  = (const float*)d_in[7];
    float* out = (float*)d_out;

    cudaFuncSetAttribute(gemm_mma<0>, cudaFuncAttributeMaxDynamicSharedMemorySize, GEMM_SMEM);
    cudaFuncSetAttribute(gemm_mma<1>, cudaFuncAttributeMaxDynamicSharedMemorySize, GEMM_SMEM);

    ln_kernel<<<NTOK, 256>>>(u, ln_g, ln_b);
    wconv_kernel<0><<<dim3(PROJ_OUT / 32, D_MODEL / 32), dim3(32, 32)>>>(W_in);
    gemm_mma<0><<<dim3(PROJ_OUT / 128, NTOK / 128), 256, GEMM_SMEM>>>(nullptr, nullptr);
    conv_dtx_kernel<<<(NTOK * D_INNER) / 256, 256>>>(conv_w, conv_b, A_log);
    scan_kernel<<<128, 256>>>();
    yconv_kernel<<<(NTOK * D_INNER) / 256, 256>>>();
    wconv_kernel<1><<<dim3(D_MODEL / 32, D_INNER / 32), dim3(32, 32)>>>(W_out);
    gemm_mma<1><<<dim3(D_MODEL / 128, NTOK / 128), 256, GEMM_SMEM>>>(u, out);
}

// round 6
// speedup vs baseline: 1.7142x; 1.0512x over previous
#include <cuda_runtime.h>
#include <cuda_bf16.h>
#include <cstdint>

#define D_MODEL  1024
#define D_STATE  128
#define D_INNER  2048
#define HEADS    1024
#define PROJ_OUT 5376
#define BATCH    2
#define SEQ      2048
#define NTOK     (BATCH*SEQ)   // 4096

#define OFF_Z  2048
#define OFF_B  4096
#define OFF_C  4224
#define OFF_DT 4352

#define K2_1 3072          // 3 * D_MODEL  (split GEMM1 K)
#define K2_2 6144          // 3 * D_INNER  (split GEMM2 K)

// ---------------- scratch (device globals) -----------------------------------
__device__ float g_zxbcdt[(size_t)NTOK * PROJ_OUT];
__device__ float g_dtx   [(size_t)NTOK * D_INNER];
__device__ float g_zsil  [(size_t)NTOK * D_INNER];
__device__ float g_decay [(size_t)NTOK * HEADS];
__device__ __nv_bfloat16 g_Ain [(size_t)NTOK * K2_1];      // [Ahi|Ahi|Alo] of ln(u)
__device__ __nv_bfloat16 g_Bin [(size_t)PROJ_OUT * K2_1];  // W_in^T split [Bhi|Blo|Bhi]
__device__ __nv_bfloat16 g_Ay  [(size_t)NTOK * K2_2];      // [Ahi|Ahi|Alo] of y*silu(z)
__device__ __nv_bfloat16 g_Bout[(size_t)D_MODEL * K2_2];   // W_out^T split

// ---------------- helpers -----------------------------------------------------
struct alignas(8) bf4 { __nv_bfloat16 v[4]; };

__device__ __forceinline__ uint32_t smem_u32(const void* p) {
    uint32_t a;
    asm("{ .reg .u64 t; cvta.to.shared.u64 t, %1; cvt.u32.u64 %0, t; }" : "=r"(a) : "l"(p));
    return a;
}
__device__ __forceinline__ void cp16(uint32_t s, const void* g) {
    asm volatile("cp.async.cg.shared.global [%0], [%1], 16;" :: "r"(s), "l"(g) : "memory");
}
#define CP_COMMIT() asm volatile("cp.async.commit_group;" ::: "memory")

__device__ __forceinline__ void ldsm_x4(uint32_t& r0, uint32_t& r1, uint32_t& r2, uint32_t& r3,
                                        uint32_t addr) {
    asm volatile("ldmatrix.sync.aligned.m8n8.x4.shared.b16 {%0,%1,%2,%3}, [%4];"
                 : "=r"(r0), "=r"(r1), "=r"(r2), "=r"(r3) : "r"(addr));
}
__device__ __forceinline__ void mma16816(float& d0, float& d1, float& d2, float& d3,
                                         uint32_t a0, uint32_t a1, uint32_t a2, uint32_t a3,
                                         uint32_t b0, uint32_t b1) {
    asm volatile("mma.sync.aligned.m16n8k16.row.col.f32.bf16.bf16.f32 "
                 "{%0,%1,%2,%3}, {%4,%5,%6,%7}, {%8,%9}, {%0,%1,%2,%3};"
                 : "+f"(d0), "+f"(d1), "+f"(d2), "+f"(d3)
                 : "r"(a0), "r"(a1), "r"(a2), "r"(a3), "r"(b0), "r"(b1));
}
__device__ __forceinline__ void split_bf16(float v, __nv_bfloat16& hi, __nv_bfloat16& lo) {
    hi = __float2bfloat16(v);
    lo = __float2bfloat16(v - __bfloat162float(hi));
}
// smem tile byte offset, row-major [128][32] bf16 with XOR swizzle for LDSM
__device__ __forceinline__ uint32_t swz(uint32_t row, uint32_t k) {
    uint32_t chunk = (k >> 3) ^ ((row >> 1) & 3);
    return row * 64 + chunk * 16 + (k & 7) * 2;
}

// ---------------- 1. LayerNorm -> split bf16 A2 ------------------------------
__global__ void __launch_bounds__(256) ln_kernel(const float* __restrict__ u,
                                                 const float* __restrict__ g,
                                                 const float* __restrict__ b) {
    __shared__ float sS[8], sQ[8], sMV[2];
    const int row = blockIdx.x;
    const int tid = threadIdx.x;
    const int warp = tid >> 5, lane = tid & 31;

    float4 v = *((const float4*)(u + (size_t)row * D_MODEL) + tid);
    float s = v.x + v.y + v.z + v.w;
    float q = v.x*v.x + v.y*v.y + v.z*v.z + v.w*v.w;
    #pragma unroll
    for (int off = 16; off > 0; off >>= 1) {
        s += __shfl_xor_sync(0xffffffffu, s, off);
        q += __shfl_xor_sync(0xffffffffu, q, off);
    }
    if (lane == 0) { sS[warp] = s; sQ[warp] = q; }
    __syncthreads();
    if (tid == 0) {
        float S = 0.f, Q = 0.f;
        #pragma unroll
        for (int i = 0; i < 8; ++i) { S += sS[i]; Q += sQ[i]; }
        float mean = S * (1.0f / D_MODEL);
        float var  = Q * (1.0f / D_MODEL) - mean * mean;
        sMV[0] = mean;
        sMV[1] = rsqrtf(var + 1e-5f);
    }
    __syncthreads();
    const float mean = sMV[0], rstd = sMV[1];
    float4 gg = ((const float4*)g)[tid];
    float4 bb = ((const float4*)b)[tid];
    float o[4];
    o[0] = (v.x - mean) * rstd * gg.x + bb.x;
    o[1] = (v.y - mean) * rstd * gg.y + bb.y;
    o[2] = (v.z - mean) * rstd * gg.z + bb.z;
    o[3] = (v.w - mean) * rstd * gg.w + bb.w;
    bf4 H, L;
    #pragma unroll
    for (int j = 0; j < 4; ++j) split_bf16(o[j], H.v[j], L.v[j]);
    const size_t rb = (size_t)row * K2_1 + tid * 4;
    *(bf4*)(g_Ain + rb)              = H;
    *(bf4*)(g_Ain + rb + D_MODEL)    = H;
    *(bf4*)(g_Ain + rb + 2*D_MODEL)  = L;
}

// ---------------- weight transpose + split: W[K,N] -> B2[N, 3K] --------------
// Output array selected IN DEVICE CODE (host naming of __device__ globals gets
// the host shadow symbol; on GB300/ATS that silently writes host RAM).
template<int PHASE>
__global__ void wconv_kernel(const float* __restrict__ W) {
    constexpr int K = PHASE ? D_INNER : D_MODEL;
    constexpr int N = PHASE ? D_MODEL : PROJ_OUT;
    __nv_bfloat16* __restrict__ Bo = PHASE ? g_Bout : g_Bin;

    __shared__ float t[32][33];
    const int tx = threadIdx.x, ty = threadIdx.y;
    const int n0 = blockIdx.x * 32, k0 = blockIdx.y * 32;
    t[ty][tx] = W[(size_t)(k0 + ty) * N + n0 + tx];
    __syncthreads();
    float v = t[tx][ty];                       // = W[k0+tx][n0+ty]
    __nv_bfloat16 hi, lo;
    split_bf16(v, hi, lo);
    const size_t r = (size_t)(n0 + ty) * 3 * K + k0 + tx;
    Bo[r]         = hi;
    Bo[r + K]     = lo;
    Bo[r + 2*K]   = hi;
}

// ---------------- bf16 mma.sync GEMM (128x128x32, 3-stage, ldmatrix) ---------
// PHASE 0: g_Ain(4096 x 3072) @ g_Bin^T (5376 x 3072) -> g_zxbcdt fp32
// PHASE 1: g_Ay (4096 x 6144) @ g_Bout^T(1024 x 6144) + u -> out fp32
template<int PHASE>
__global__ void __launch_bounds__(256) gemm_mma(const float* __restrict__ R,
                                                float* __restrict__ Cout) {
    constexpr int K2 = PHASE ? K2_2 : K2_1;
    constexpr int NC = PHASE ? D_MODEL : PROJ_OUT;
    constexpr int NITER = K2 / 32;

    const __nv_bfloat16* Asrc = PHASE ? g_Ay  : g_Ain;
    const __nv_bfloat16* Bsrc = PHASE ? g_Bout : g_Bin;
    float* C = PHASE ? Cout : g_zxbcdt;

    __shared__ char smemraw[3 * 16384];      // 3 stages x (A 8KB + B 8KB) = 48KB
    const uint32_t sb = smem_u32(smemraw);

    const int tid = threadIdx.x;
    const int wid = tid >> 5, lane = tid & 31;
    const int wm = wid & 1, wn = wid >> 1;          // warp tile: 64 x 32
    const int m0 = blockIdx.y * 128, n0 = blockIdx.x * 128;
    const __nv_bfloat16* Ag = Asrc + (size_t)m0 * K2;
    const __nv_bfloat16* Bg = Bsrc + (size_t)n0 * K2;

    auto load_stage = [&](int it, int st) {
        const int k0 = it * 32;
        const uint32_t base = sb + st * 16384;
        #pragma unroll
        for (int i = 0; i < 2; ++i) {
            const int idx = tid + i * 256;          // 0..511 -> (row, chunk)
            const int row = idx >> 2, ch = idx & 3;
            const uint32_t off = swz(row, ch * 8);
            cp16(base        + off, Ag + (size_t)row * K2 + k0 + ch * 8);
            cp16(base + 8192 + off, Bg + (size_t)row * K2 + k0 + ch * 8);
        }
    };

    float acc[4][4][4];
    #pragma unroll
    for (int mt = 0; mt < 4; ++mt)
        #pragma unroll
        for (int nt = 0; nt < 4; ++nt)
            #pragma unroll
            for (int r = 0; r < 4; ++r) acc[mt][nt][r] = 0.f;

    load_stage(0, 0); CP_COMMIT();
    load_stage(1, 1); CP_COMMIT();

    // ldmatrix source coordinates (intra-tile)
    const uint32_t a_row = wm * 64 + (lane & 15);
    const uint32_t a_k   = (lane >> 4) * 8;
    const uint32_t b_row = wn * 32 + ((lane >> 4) & 1) * 8 + (lane & 7);
    const uint32_t b_k   = ((lane >> 3) & 1) * 8;

    int st = 0;
    for (int it = 0; it < NITER; ++it) {
        asm volatile("cp.async.wait_group 1;" ::: "memory");
        __syncthreads();
        if (it + 2 < NITER) load_stage(it + 2, (st + 2) % 3);
        CP_COMMIT();

        const uint32_t abase = sb + st * 16384;
        const uint32_t bbase = abase + 8192;
        #pragma unroll
        for (int ks = 0; ks < 2; ++ks) {
            uint32_t a[4][4], b[4][2];
            #pragma unroll
            for (int mt = 0; mt < 4; ++mt)
                ldsm_x4(a[mt][0], a[mt][1], a[mt][2], a[mt][3],
                        abase + swz(a_row + mt * 16, ks * 16 + a_k));
            #pragma unroll
            for (int nt2 = 0; nt2 < 2; ++nt2)
                ldsm_x4(b[nt2*2][0], b[nt2*2][1], b[nt2*2+1][0], b[nt2*2+1][1],
                        bbase + swz(b_row + nt2 * 16, ks * 16 + b_k));
            #pragma unroll
            for (int mt = 0; mt < 4; ++mt)
                #pragma unroll
                for (int nt = 0; nt < 4; ++nt)
                    mma16816(acc[mt][nt][0], acc[mt][nt][1], acc[mt][nt][2], acc[mt][nt][3],
                             a[mt][0], a[mt][1], a[mt][2], a[mt][3], b[nt][0], b[nt][1]);
        }
        st = (st + 1) % 3;
    }

    // epilogue
    const int rbase = m0 + wm * 64 + (lane >> 2);
    const int cbase = n0 + wn * 32 + 2 * (lane & 3);
    #pragma unroll
    for (int mt = 0; mt < 4; ++mt) {
        #pragma unroll
        for (int nt = 0; nt < 4; ++nt) {
            const int rr0 = rbase + mt * 16;
            const int cc  = cbase + nt * 8;
            float2 v0 = make_float2(acc[mt][nt][0], acc[mt][nt][1]);
            float2 v1 = make_float2(acc[mt][nt][2], acc[mt][nt][3]);
            if (PHASE == 1) {
                float2 r0 = *(const float2*)&R[(size_t)rr0 * NC + cc];
                float2 r1 = *(const float2*)&R[(size_t)(rr0 + 8) * NC + cc];
                v0.x += r0.x; v0.y += r0.y;
                v1.x += r1.x; v1.y += r1.y;
            }
            *(float2*)&C[(size_t)rr0 * NC + cc]       = v0;
            *(float2*)&C[(size_t)(rr0 + 8) * NC + cc] = v1;
        }
    }
}

// ---------------- conv + silu + softplus(dt) + decay + silu(z) ---------------
__global__ void __launch_bounds__(256) conv_dtx_kernel(const float* __restrict__ conv_w,
                                                       const float* __restrict__ conv_b,
                                                       const float* __restrict__ A_log) {
    const int idx = blockIdx.x * 256 + threadIdx.x;
    const int c  = idx & (D_INNER - 1);
    const int bt = idx >> 11;
    const int t  = bt & (SEQ - 1);
    const float* row = g_zxbcdt + (size_t)bt * PROJ_OUT;

    float acc = conv_b[c];
    #pragma unroll
    for (int k = 0; k < 4; ++k) {
        int tt = t - 3 + k;
        if (tt >= 0)
            acc += conv_w[c * 4 + k] * g_zxbcdt[(size_t)(bt - 3 + k) * PROJ_OUT + c];
    }
    float xs = acc / (1.f + expf(-acc));
    int h = c >> 1;
    float dtraw = row[OFF_DT + h];
    float dtp = (dtraw > 20.f) ? dtraw : log1pf(expf(dtraw));
    g_dtx[idx] = dtp * xs;
    float z = row[OFF_Z + c];
    g_zsil[idx] = z / (1.f + expf(-z));
    if (!(c & 1))
        g_decay[(size_t)bt * HEADS + h] = expf(dtp * (-expf(A_log[h])));
}

// ---------------- SSM scan (writers emit split bf16 into g_Ay directly) -------
__device__ __forceinline__ unsigned long long pk2(float x, float y) {
    unsigned long long r;
    asm("mov.b64 %0, {%1, %2};" : "=l"(r) : "f"(x), "f"(y));
    return r;
}
__device__ __forceinline__ void upk2(unsigned long long v, float& x, float& y) {
    asm("mov.b64 {%0, %1}, %2;" : "=f"(x), "=f"(y) : "l"(v));
}
__device__ __forceinline__ unsigned long long ffma2_(unsigned long long a,
                                                     unsigned long long b,
                                                     unsigned long long c) {
    unsigned long long d;
    asm("fma.rn.f32x2 %0, %1, %2, %3;" : "=l"(d) : "l"(a), "l"(b), "l"(c));
    return d;
}
__device__ __forceinline__ unsigned long long fmul2_(unsigned long long a,
                                                     unsigned long long b) {
    unsigned long long d;
    asm("mul.rn.f32x2 %0, %1, %2;" : "=l"(d) : "l"(a), "l"(b));
    return d;
}

#define CHUNK 32
__global__ void __launch_bounds__(256, 1) scan_kernel() {
    __shared__ float sB[CHUNK][128];
    __shared__ float sC[CHUNK][128];
    __shared__ float sDec[CHUNK][16];
    __shared__ float sKx[CHUNK][32];
    __shared__ float sZ[CHUNK][32];

    const int tid = threadIdx.x;
    const int warp = tid >> 5, lane = tid & 31;
    const int batch = blockIdx.x >> 6;
    const int hbase = (blockIdx.x & 63) << 4;
    const int lhA = warp << 1;
    const int ni = lane << 2;

    unsigned long long a00 = 0, a01 = 0, a10 = 0, a11 = 0;
    unsigned long long b00 = 0, b01 = 0, b10 = 0, b11 = 0;

    const float* zx = g_zxbcdt + (size_t)batch * SEQ * PROJ_OUT;
    const int sel = lane >> 3;
    const bool writer = (lane & 7) == 0;
    const int zloc = (lhA << 1) + sel;
    const int col = (hbase << 1) + zloc;          // channel in 0..2047

    for (int ch = 0; ch < SEQ / CHUNK; ++ch) {
        const int t0 = ch << 5;
        __syncthreads();
        {
            const float* rb = zx + (size_t)t0 * PROJ_OUT;
            #pragma unroll
            for (int i = tid; i < CHUNK * 32; i += 256) {
                int st = i >> 5, j = (i & 31) << 2;
                const float* p = rb + (size_t)st * PROJ_OUT;
                *(float4*)&sB[st][j] = *(const float4*)(p + OFF_B + j);
                *(float4*)&sC[st][j] = *(const float4*)(p + OFF_C + j);
            }
            #pragma unroll
            for (int i = tid; i < CHUNK * 16; i += 256) {
                int st = i >> 4, h = i & 15;
                sDec[st][h] = g_decay[(size_t)(batch * SEQ + t0 + st) * HEADS + hbase + h];
            }
            #pragma unroll
            for (int i = tid; i < CHUNK * 32; i += 256) {
                int st = i >> 5, j = i & 31;
                size_t gi = (size_t)(batch * SEQ + t0 + st) * D_INNER + ((size_t)hbase << 1) + j;
                sKx[st][j] = g_dtx[gi];
                sZ[st][j]  = g_zsil[gi];
            }
        }
        __syncthreads();

        #pragma unroll 2
        for (int tl = 0; tl < CHUNK; ++tl) {
            unsigned long long B01 = *(const unsigned long long*)&sB[tl][ni];
            unsigned long long B23 = *(const unsigned long long*)&sB[tl][ni + 2];
            unsigned long long C01 = *(const unsigned long long*)&sC[tl][ni];
            unsigned long long C23 = *(const unsigned long long*)&sC[tl][ni + 2];

            float decA = sDec[tl][lhA];
            float2 kxA = *(const float2*)&sKx[tl][lhA << 1];
            unsigned long long dA  = pk2(decA, decA);
            unsigned long long kA0 = pk2(kxA.x, kxA.x);
            unsigned long long kA1 = pk2(kxA.y, kxA.y);
            a00 = ffma2_(dA, a00, fmul2_(kA0, B01));
            a01 = ffma2_(dA, a01, fmul2_(kA0, B23));
            a10 = ffma2_(dA, a10, fmul2_(kA1, B01));
            a11 = ffma2_(dA, a11, fmul2_(kA1, B23));

            float decB = sDec[tl][lhA + 1];
            float2 kxB = *(const float2*)&sKx[tl][(lhA << 1) + 2];
            unsigned long long dB  = pk2(decB, decB);
            unsigned long long kB0 = pk2(kxB.x, kxB.x);
            unsigned long long kB1 = pk2(kxB.y, kxB.y);
            b00 = ffma2_(dB, b00, fmul2_(kB0, B01));
            b01 = ffma2_(dB, b01, fmul2_(kB0, B23));
            b10 = ffma2_(dB, b10, fmul2_(kB1, B01));
            b11 = ffma2_(dB, b11, fmul2_(kB1, B23));

            unsigned long long dp;
            float fx, fy;
            dp = ffma2_(a01, C23, fmul2_(a00, C01)); upk2(dp, fx, fy); float y0 = fx + fy;
            dp = ffma2_(a11, C23, fmul2_(a10, C01)); upk2(dp, fx, fy); float y1 = fx + fy;
            dp = ffma2_(b01, C23, fmul2_(b00, C01)); upk2(dp, fx, fy); float y2 = fx + fy;
            dp = ffma2_(b11, C23, fmul2_(b10, C01)); upk2(dp, fx, fy); float y3 = fx + fy;

            float t0v = (lane < 16) ? y2 : y0;
            float u0 = __shfl_xor_sync(0xffffffffu, t0v, 16);
            if (lane < 16) y0 += u0; else y2 += u0;
            float t1v = (lane < 16) ? y3 : y1;
            float u1 = __shfl_xor_sync(0xffffffffu, t1v, 16);
            if (lane < 16) y1 += u1; else y3 += u1;
            float v0 = (lane < 16) ? y0 : y2;
            float v1 = (lane < 16) ? y1 : y3;
            float tv = (lane & 8) ? v0 : v1;
            float uv = __shfl_xor_sync(0xffffffffu, tv, 8);
            if (lane & 8) v1 += uv; else v0 += uv;
            float v = (lane & 8) ? v1 : v0;
            v += __shfl_xor_sync(0xffffffffu, v, 4);
            v += __shfl_xor_sync(0xffffffffu, v, 2);
            v += __shfl_xor_sync(0xffffffffu, v, 1);

            if (writer) {
                float yv = v * sZ[tl][zloc];
                __nv_bfloat16 hi, lo;
                split_bf16(yv, hi, lo);
                const size_t base = (size_t)(batch * SEQ + t0 + tl) * K2_2 + col;
                g_Ay[base]              = hi;
                g_Ay[base + D_INNER]    = hi;
                g_Ay[base + 2*D_INNER]  = lo;
            }
        }
    }
}

// ---------------- launch ------------------------------------------------------
extern "C" void kernel_launch(void* const* d_in, const int* in_sizes, int n_in,
                              void* d_out, int out_size) {
    const float* u      = (const float*)d_in[0];
    const float* W_in   = (const float*)d_in[1];
    const float* conv_w = (const float*)d_in[2];
    const float* conv_b = (const float*)d_in[3];
    const float* W_out  = (const float*)d_in[4];
    const float* ln_g   = (const float*)d_in[5];
    const float* ln_b   = (const float*)d_in[6];
    const float* A_log  = (const float*)d_in[7];
    float* out = (float*)d_out;

    ln_kernel<<<NTOK, 256>>>(u, ln_g, ln_b);
    wconv_kernel<0><<<dim3(PROJ_OUT / 32, D_MODEL / 32), dim3(32, 32)>>>(W_in);
    gemm_mma<0><<<dim3(PROJ_OUT / 128, NTOK / 128), 256>>>(nullptr, nullptr);
    conv_dtx_kernel<<<(NTOK * D_INNER) / 256, 256>>>(conv_w, conv_b, A_log);
    scan_kernel<<<128, 256>>>();
    wconv_kernel<1><<<dim3(D_MODEL / 32, D_INNER / 32), dim3(32, 32)>>>(W_out);
    gemm_mma<1><<<dim3(D_MODEL / 128, NTOK / 128), 256>>>(u, out);
}